// round 2
// baseline (speedup 1.0000x reference)
#include <cuda_runtime.h>
#include <cuda_bf16.h>
#include <math.h>

// Problem constants
#define BATCH 2
#define TT    2048
#define TOK   (BATCH * TT)      // 4096 tokens
#define DD    1024
#define HH    16
#define HDIM  64
#define INNER (HH * HDIM)       // 1024
#define VOCAB 32000
#define FFN   (4 * DD)          // 4096

// ---------------- scratch (static device globals; no allocation) ----------------
__device__ float g_h  [TOK * DD];        // residual stream
__device__ float g_h1 [TOK * DD];        // ln output (reused for ln1 and ln2)
__device__ float g_qkv[TOK * 3 * INNER]; // qkv
__device__ float g_att[TOK * INNER];     // attention output (B,T,INNER)
__device__ float g_ff1[TOK * FFN];       // gelu(h2@w1+b1)

// ---------------- block reduction (256 threads) ----------------
__device__ __forceinline__ float block_sum256(float v) {
    __shared__ float red[8];
    const unsigned FULL = 0xffffffffu;
    #pragma unroll
    for (int o = 16; o > 0; o >>= 1) v += __shfl_down_sync(FULL, v, o);
    __syncthreads();                 // protect red[] from previous use
    if ((threadIdx.x & 31) == 0) red[threadIdx.x >> 5] = v;
    __syncthreads();
    float s = 0.f;
    #pragma unroll
    for (int i = 0; i < 8; i++) s += red[i];
    return s;
}

// ---------------- token fetch: robust to int32 vs int64 layout ----------------
// Viewed as int32, an int64 token buffer is [tok0, 0, tok1, 0, ...] (tokens < 2^31
// => high words are 0). If the first 8 odd int32 slots are all zero, treat the
// buffer as int64; otherwise int32. P(false positive with real int32 tokens) ~ 32000^-8.
__device__ __forceinline__ int fetch_token(const void* xraw, int t) {
    const int* x32 = (const int*)xraw;
    bool is64 = true;
    #pragma unroll
    for (int i = 0; i < 8; i++) {
        if (x32[2 * i + 1] != 0) is64 = false;
    }
    return is64 ? (int)(((const long long*)xraw)[t]) : x32[t];
}

// ---------------- embed + pos + LN1 (one block per token, 256 thr) ----------------
__global__ void embed_ln_kernel(const void* __restrict__ x,
                                const float* __restrict__ emb,
                                const float* __restrict__ pos,
                                const float* __restrict__ g,
                                const float* __restrict__ b,
                                float* __restrict__ h,
                                float* __restrict__ h1) {
    const int t    = blockIdx.x;          // 0..4095
    const int tpos = t & (TT - 1);
    const int tok = fetch_token(x, t);
    const float* e = emb + (size_t)tok * DD;
    const float* p = pos + (size_t)tpos * DD;

    float local[4];
    float s = 0.f;
    #pragma unroll
    for (int i = 0; i < 4; i++) {
        int idx = threadIdx.x + i * 256;
        float v = e[idx] + p[idx];
        local[i] = v;
        h[(size_t)t * DD + idx] = v;
        s += v;
    }
    float S = block_sum256(s);
    float mu = S * (1.0f / DD);
    float s2 = 0.f;
    #pragma unroll
    for (int i = 0; i < 4; i++) { float d = local[i] - mu; s2 += d * d; }
    float V = block_sum256(s2);
    float rstd = rsqrtf(V * (1.0f / DD) + 1e-5f);
    #pragma unroll
    for (int i = 0; i < 4; i++) {
        int idx = threadIdx.x + i * 256;
        h1[(size_t)t * DD + idx] = (local[i] - mu) * rstd * g[idx] + b[idx];
    }
}

// ---------------- LN only (one block per token) ----------------
__global__ void ln_kernel(const float* __restrict__ h,
                          const float* __restrict__ g,
                          const float* __restrict__ b,
                          float* __restrict__ out) {
    const int t = blockIdx.x;
    float local[4];
    float s = 0.f;
    #pragma unroll
    for (int i = 0; i < 4; i++) {
        int idx = threadIdx.x + i * 256;
        float v = h[(size_t)t * DD + idx];
        local[i] = v;
        s += v;
    }
    float S = block_sum256(s);
    float mu = S * (1.0f / DD);
    float s2 = 0.f;
    #pragma unroll
    for (int i = 0; i < 4; i++) { float d = local[i] - mu; s2 += d * d; }
    float V = block_sum256(s2);
    float rstd = rsqrtf(V * (1.0f / DD) + 1e-5f);
    #pragma unroll
    for (int i = 0; i < 4; i++) {
        int idx = threadIdx.x + i * 256;
        out[(size_t)t * DD + idx] = (local[i] - mu) * rstd * g[idx] + b[idx];
    }
}

// ---------------- SGEMM: D = A(MxK) @ B(KxN) [+bias] [gelu] [+C] ----------------
// 128x128 tile, BK=8, 256 threads, 8x8 per-thread micro-tile.
// All dims are multiples of the tile sizes for this problem (no bounds checks).
template<int DO_BIAS, int DO_ADDC, int DO_GELU>
__global__ __launch_bounds__(256)
void sgemm_kernel(int M, int N, int K,
                  const float* __restrict__ A,
                  const float* __restrict__ B,
                  const float* __restrict__ Cadd,
                  const float* __restrict__ bias,
                  float* __restrict__ D) {
    __shared__ float As[8][128];
    __shared__ float Bs[8][128];

    const int tid = threadIdx.x;
    const int tx = tid & 15;        // 0..15  (col group)
    const int ty = tid >> 4;        // 0..15  (row group)

    const int bx = blockIdx.x;      // N tile
    const int by = blockIdx.y;      // M tile

    const float* Ablk = A + (size_t)by * 128 * K;
    const float* Bblk = B + (size_t)bx * 128;

    const int arow = tid >> 1;         // 0..127
    const int acol = (tid & 1) * 4;    // 0 or 4
    const int brow = tid >> 5;         // 0..7
    const int bcol = (tid & 31) * 4;   // 0..124

    float acc[8][8];
    #pragma unroll
    for (int i = 0; i < 8; i++)
        #pragma unroll
        for (int j = 0; j < 8; j++) acc[i][j] = 0.f;

    for (int k0 = 0; k0 < K; k0 += 8) {
        float4 a  = *(const float4*)(Ablk + (size_t)arow * K + k0 + acol);
        float4 bv = *(const float4*)(Bblk + (size_t)(k0 + brow) * N + bcol);
        As[acol + 0][arow] = a.x;
        As[acol + 1][arow] = a.y;
        As[acol + 2][arow] = a.z;
        As[acol + 3][arow] = a.w;
        *(float4*)&Bs[brow][bcol] = bv;
        __syncthreads();

        #pragma unroll
        for (int kk = 0; kk < 8; kk++) {
            float ra[8], rb[8];
            #pragma unroll
            for (int i = 0; i < 8; i++) ra[i] = As[kk][ty * 8 + i];
            #pragma unroll
            for (int j = 0; j < 8; j++) rb[j] = Bs[kk][tx * 8 + j];
            #pragma unroll
            for (int i = 0; i < 8; i++)
                #pragma unroll
                for (int j = 0; j < 8; j++) acc[i][j] += ra[i] * rb[j];
        }
        __syncthreads();
    }

    const int row0 = by * 128 + ty * 8;
    const int col0 = bx * 128 + tx * 8;
    #pragma unroll
    for (int i = 0; i < 8; i++) {
        size_t off = (size_t)(row0 + i) * N + col0;
        #pragma unroll
        for (int j = 0; j < 8; j++) {
            float v = acc[i][j];
            if (DO_BIAS) v += bias[col0 + j];
            if (DO_GELU) v = v * normcdff(v);   // exact gelu: x * Phi(x)
            if (DO_ADDC) v += Cadd[off + j];
            D[off + j] = v;
        }
    }
}

// ---------------- flash attention ----------------
// grid (T/64, H, B), 64 threads. Each thread owns one query row:
// q[64] + acc[64] in registers, K/V 64x64 tiles in SMEM, online softmax
// over 32-wide score chunks (registers).
__global__ __launch_bounds__(64)
void flash_attn_kernel(const float* __restrict__ qkv, float* __restrict__ out) {
    const int tid = threadIdx.x;        // 0..63
    const int qt = blockIdx.x;
    const int hh = blockIdx.y;
    const int b  = blockIdx.z;

    __shared__ float k_sm[64 * 64];
    __shared__ float v_sm[64 * 64];

    const int q_row = qt * 64 + tid;
    const float* qp = qkv + ((size_t)(b * TT + q_row)) * (3 * INNER) + hh * HDIM;

    float q[64], acc[64];
    #pragma unroll
    for (int d = 0; d < 64; d++) { q[d] = qp[d] * 0.125f; acc[d] = 0.f; }
    float m = -3.0e38f, l = 0.f;

    for (int kt = 0; kt <= qt; kt++) {
        const float* kb = qkv + ((size_t)(b * TT + kt * 64)) * (3 * INNER) + INNER + hh * HDIM;
        const float* vb = kb + INNER;
        __syncthreads();
        for (int r = 0; r < 64; r++) {
            k_sm[r * 64 + tid] = kb[(size_t)r * (3 * INNER) + tid];
            v_sm[r * 64 + tid] = vb[(size_t)r * (3 * INNER) + tid];
        }
        __syncthreads();

        const int valid = q_row - kt * 64;   // j <= valid are unmasked
        #pragma unroll
        for (int c = 0; c < 2; c++) {
            float s[32];
            float mt = -3.0e38f;
            for (int j = 0; j < 32; j++) {
                const int jj = c * 32 + j;
                float sv;
                if (jj <= valid) {
                    sv = 0.f;
                    #pragma unroll
                    for (int d = 0; d < 64; d++) sv += q[d] * k_sm[jj * 64 + d];
                } else {
                    sv = -3.0e38f;
                }
                s[j] = sv;
                mt = fmaxf(mt, sv);
            }
            if (mt > m) {
                float corr = expf(m - mt);
                l *= corr;
                #pragma unroll
                for (int d = 0; d < 64; d++) acc[d] *= corr;
                m = mt;
            }
            for (int j = 0; j < 32; j++) {
                float p = expf(s[j] - m);     // masked -> exp(-huge) = 0
                l += p;
                const int jj = c * 32 + j;
                #pragma unroll
                for (int d = 0; d < 64; d++) acc[d] += p * v_sm[jj * 64 + d];
            }
        }
    }

    const float inv = 1.0f / l;
    float* op = out + ((size_t)(b * TT + q_row)) * INNER + hh * HDIM;
    #pragma unroll
    for (int d = 0; d < 64; d++) op[d] = acc[d] * inv;
}

// ---------------- launch ----------------
extern "C" void kernel_launch(void* const* d_in, const int* in_sizes, int n_in,
                              void* d_out, int out_size) {
    const void*      x      = d_in[0];
    const float*     emb    = (const float*)d_in[1];
    const float*     pos    = (const float*)d_in[2];
    const float*     w_qkv  = (const float*)d_in[3];
    const float*     w_out  = (const float*)d_in[4];
    const float*     ln1_g  = (const float*)d_in[5];
    const float*     ln1_b  = (const float*)d_in[6];
    const float*     ln2_g  = (const float*)d_in[7];
    const float*     ln2_b  = (const float*)d_in[8];
    const float*     w_ffn1 = (const float*)d_in[9];
    const float*     b_ffn1 = (const float*)d_in[10];
    const float*     w_ffn2 = (const float*)d_in[11];
    const float*     b_ffn2 = (const float*)d_in[12];
    const float*     w_head = (const float*)d_in[13];
    const float*     b_head = (const float*)d_in[14];
    float* out = (float*)d_out;

    float *h, *h1, *qkv, *att, *ff1;
    cudaGetSymbolAddress((void**)&h,   g_h);
    cudaGetSymbolAddress((void**)&h1,  g_h1);
    cudaGetSymbolAddress((void**)&qkv, g_qkv);
    cudaGetSymbolAddress((void**)&att, g_att);
    cudaGetSymbolAddress((void**)&ff1, g_ff1);

    // 1. embed + pos + ln1
    embed_ln_kernel<<<TOK, 256>>>(x, emb, pos, ln1_g, ln1_b, h, h1);

    // 2. qkv = h1 @ w_qkv   (4096 x 3072 x 1024)
    sgemm_kernel<0,0,0><<<dim3(3 * INNER / 128, TOK / 128), 256>>>(
        TOK, 3 * INNER, DD, h1, w_qkv, nullptr, nullptr, qkv);

    // 3. flash attention -> att (B,T,INNER)
    flash_attn_kernel<<<dim3(TT / 64, HH, BATCH), 64>>>(qkv, att);

    // 4. h = h + att @ w_out  (4096 x 1024 x 1024, residual epilogue, in place on h)
    sgemm_kernel<0,1,0><<<dim3(DD / 128, TOK / 128), 256>>>(
        TOK, DD, INNER, att, w_out, h, nullptr, h);

    // 5. h2 = ln2(h)
    ln_kernel<<<TOK, 256>>>(h, ln2_g, ln2_b, h1);

    // 6. ff1 = gelu(h2 @ w_ffn1 + b_ffn1)  (4096 x 4096 x 1024)
    sgemm_kernel<1,0,1><<<dim3(FFN / 128, TOK / 128), 256>>>(
        TOK, FFN, DD, h1, w_ffn1, nullptr, b_ffn1, ff1);

    // 7. h = h + ff1 @ w_ffn2 + b_ffn2  (4096 x 1024 x 4096)
    sgemm_kernel<1,1,0><<<dim3(DD / 128, TOK / 128), 256>>>(
        TOK, DD, FFN, ff1, w_ffn2, h, b_ffn2, h);

    // 8. logits = h @ w_head + b_head  (4096 x 32000 x 1024)
    sgemm_kernel<1,0,0><<<dim3(VOCAB / 128, TOK / 128), 256>>>(
        TOK, VOCAB, DD, h, w_head, nullptr, b_head, out);
}

// round 3
// speedup vs baseline: 2.3871x; 2.3871x over previous
#include <cuda_runtime.h>
#include <cuda_bf16.h>
#include <math.h>

// Problem constants
#define BATCH 2
#define TT    2048
#define TOK   (BATCH * TT)      // 4096 tokens
#define DD    1024
#define HH    16
#define HDIM  64
#define INNER (HH * HDIM)       // 1024
#define VOCAB 32000
#define FFN   (4 * DD)          // 4096

// ---------------- scratch (static device globals; no allocation) ----------------
__device__ float g_h  [TOK * DD];
__device__ float g_h1 [TOK * DD];
__device__ float g_qkv[TOK * 3 * INNER];
__device__ float g_att[TOK * INNER];
__device__ float g_ff1[TOK * FFN];

// ---------------- block reduction (256 threads) ----------------
__device__ __forceinline__ float block_sum256(float v) {
    __shared__ float red[8];
    const unsigned FULL = 0xffffffffu;
    #pragma unroll
    for (int o = 16; o > 0; o >>= 1) v += __shfl_down_sync(FULL, v, o);
    __syncthreads();
    if ((threadIdx.x & 31) == 0) red[threadIdx.x >> 5] = v;
    __syncthreads();
    float s = 0.f;
    #pragma unroll
    for (int i = 0; i < 8; i++) s += red[i];
    return s;
}

// ---------------- token fetch: robust to int32 vs int64 layout ----------------
__device__ __forceinline__ int fetch_token(const void* xraw, int t) {
    const int* x32 = (const int*)xraw;
    bool is64 = true;
    #pragma unroll
    for (int i = 0; i < 8; i++) {
        if (x32[2 * i + 1] != 0) is64 = false;
    }
    return is64 ? (int)(((const long long*)xraw)[t]) : x32[t];
}

// ---------------- embed + pos + LN1 ----------------
__global__ void embed_ln_kernel(const void* __restrict__ x,
                                const float* __restrict__ emb,
                                const float* __restrict__ pos,
                                const float* __restrict__ g,
                                const float* __restrict__ b,
                                float* __restrict__ h,
                                float* __restrict__ h1) {
    const int t    = blockIdx.x;
    const int tpos = t & (TT - 1);
    const int tok = fetch_token(x, t);
    const float* e = emb + (size_t)tok * DD;
    const float* p = pos + (size_t)tpos * DD;

    float local[4];
    float s = 0.f;
    #pragma unroll
    for (int i = 0; i < 4; i++) {
        int idx = threadIdx.x + i * 256;
        float v = e[idx] + p[idx];
        local[i] = v;
        h[(size_t)t * DD + idx] = v;
        s += v;
    }
    float S = block_sum256(s);
    float mu = S * (1.0f / DD);
    float s2 = 0.f;
    #pragma unroll
    for (int i = 0; i < 4; i++) { float d = local[i] - mu; s2 += d * d; }
    float V = block_sum256(s2);
    float rstd = rsqrtf(V * (1.0f / DD) + 1e-5f);
    #pragma unroll
    for (int i = 0; i < 4; i++) {
        int idx = threadIdx.x + i * 256;
        h1[(size_t)t * DD + idx] = (local[i] - mu) * rstd * g[idx] + b[idx];
    }
}

// ---------------- LN only ----------------
__global__ void ln_kernel(const float* __restrict__ h,
                          const float* __restrict__ g,
                          const float* __restrict__ b,
                          float* __restrict__ out) {
    const int t = blockIdx.x;
    float local[4];
    float s = 0.f;
    #pragma unroll
    for (int i = 0; i < 4; i++) {
        int idx = threadIdx.x + i * 256;
        float v = h[(size_t)t * DD + idx];
        local[i] = v;
        s += v;
    }
    float S = block_sum256(s);
    float mu = S * (1.0f / DD);
    float s2 = 0.f;
    #pragma unroll
    for (int i = 0; i < 4; i++) { float d = local[i] - mu; s2 += d * d; }
    float V = block_sum256(s2);
    float rstd = rsqrtf(V * (1.0f / DD) + 1e-5f);
    #pragma unroll
    for (int i = 0; i < 4; i++) {
        int idx = threadIdx.x + i * 256;
        out[(size_t)t * DD + idx] = (local[i] - mu) * rstd * g[idx] + b[idx];
    }
}

// ================= tensor-core GEMM (bf16x3 split emulating fp32) =================
// D(MxN) = A(MxK) @ B(KxN) [+bias] [gelu] [+C]
// A,B,C,D fp32 row-major. A/B split on the fly into bf16 hi+lo.
// CTA tile 128x128, BK=32, 256 threads = 8 warps in 4(M) x 2(N); warp tile 32x64.

#define LDA_S 40    // A smem row stride (elems): 128 rows x 40
#define LDB_S 136   // B smem row stride (elems): 32 rows x 136

__device__ __forceinline__ unsigned smem_addr_u32(const void* p) {
    return (unsigned)__cvta_generic_to_shared(p);
}

__device__ __forceinline__ void ldmatrix_x4(unsigned* r, unsigned addr) {
    asm volatile("ldmatrix.sync.aligned.m8n8.x4.shared.b16 {%0,%1,%2,%3}, [%4];"
                 : "=r"(r[0]), "=r"(r[1]), "=r"(r[2]), "=r"(r[3]) : "r"(addr));
}
__device__ __forceinline__ void ldmatrix_x4_trans(unsigned* r, unsigned addr) {
    asm volatile("ldmatrix.sync.aligned.m8n8.x4.trans.shared.b16 {%0,%1,%2,%3}, [%4];"
                 : "=r"(r[0]), "=r"(r[1]), "=r"(r[2]), "=r"(r[3]) : "r"(addr));
}
__device__ __forceinline__ void mma_bf16(float* c, const unsigned* a, const unsigned* b) {
    asm volatile("mma.sync.aligned.m16n8k16.row.col.f32.bf16.bf16.f32 "
                 "{%0,%1,%2,%3}, {%4,%5,%6,%7}, {%8,%9}, {%0,%1,%2,%3};"
                 : "+f"(c[0]), "+f"(c[1]), "+f"(c[2]), "+f"(c[3])
                 : "r"(a[0]), "r"(a[1]), "r"(a[2]), "r"(a[3]), "r"(b[0]), "r"(b[1]));
}

__device__ __forceinline__ unsigned pack_bf16x2(__nv_bfloat16 a, __nv_bfloat16 b) {
    __nv_bfloat162 p = __halves2bfloat162(a, b);   // (lo=a, hi=b) -> bits [a | b<<16]
    return *(unsigned*)&p;
}

template<int DO_BIAS, int DO_ADDC, int DO_GELU>
__global__ __launch_bounds__(256)
void gemm_tc_kernel(int M, int N, int K,
                    const float* __restrict__ A,
                    const float* __restrict__ B,
                    const float* __restrict__ Cadd,
                    const float* __restrict__ bias,
                    float* __restrict__ D) {
    __shared__ __align__(16) __nv_bfloat16 As_hi[128 * LDA_S];
    __shared__ __align__(16) __nv_bfloat16 As_lo[128 * LDA_S];
    __shared__ __align__(16) __nv_bfloat16 Bs_hi[32 * LDB_S];
    __shared__ __align__(16) __nv_bfloat16 Bs_lo[32 * LDB_S];

    const int tid   = threadIdx.x;
    const int lane  = tid & 31;
    const int warp  = tid >> 5;        // 0..7
    const int wm    = warp & 3;        // M group (0..3) -> rows wm*32
    const int wn    = warp >> 2;       // N group (0..1) -> cols wn*64

    const int bx = blockIdx.x;         // N tile
    const int by = blockIdx.y;         // M tile

    const float* Ablk = A + (size_t)by * 128 * K;
    const float* Bblk = B + (size_t)bx * 128;

    float acc[2][8][4];
    #pragma unroll
    for (int i = 0; i < 2; i++)
        #pragma unroll
        for (int j = 0; j < 8; j++)
            #pragma unroll
            for (int q = 0; q < 4; q++) acc[i][j][q] = 0.f;

    // ldmatrix source addresses (per-lane), as element offsets
    // A: row = wm*32 + mt*16 + (lane&15), col = ks*16 + (lane>>4)*8
    const int a_row = wm * 32 + (lane & 15);
    const int a_col = (lane >> 4) * 8;
    // B: row = ks*16 + (lane&15), col = wn*64 + ntp*16 + (lane>>4)*8
    const int b_row = (lane & 15);
    const int b_col = wn * 64 + (lane >> 4) * 8;

    for (int k0 = 0; k0 < K; k0 += 32) {
        __syncthreads();   // protect smem from previous iteration's reads

        // ---- load + split A tile: 128 x 32 fp32 -> hi/lo bf16 ----
        #pragma unroll
        for (int i = 0; i < 4; i++) {
            int f4  = tid + 256 * i;          // 0..1023
            int row = f4 >> 3;                // 0..127
            int c4  = f4 & 7;                 // 0..7
            float4 v = *(const float4*)(Ablk + (size_t)row * K + k0 + c4 * 4);
            __nv_bfloat16 h0 = __float2bfloat16(v.x);
            __nv_bfloat16 h1 = __float2bfloat16(v.y);
            __nv_bfloat16 h2 = __float2bfloat16(v.z);
            __nv_bfloat16 h3 = __float2bfloat16(v.w);
            __nv_bfloat16 l0 = __float2bfloat16(v.x - __bfloat162float(h0));
            __nv_bfloat16 l1 = __float2bfloat16(v.y - __bfloat162float(h1));
            __nv_bfloat16 l2 = __float2bfloat16(v.z - __bfloat162float(h2));
            __nv_bfloat16 l3 = __float2bfloat16(v.w - __bfloat162float(h3));
            uint2 ph = make_uint2(pack_bf16x2(h0, h1), pack_bf16x2(h2, h3));
            uint2 pl = make_uint2(pack_bf16x2(l0, l1), pack_bf16x2(l2, l3));
            *(uint2*)&As_hi[row * LDA_S + c4 * 4] = ph;
            *(uint2*)&As_lo[row * LDA_S + c4 * 4] = pl;
        }
        // ---- load + split B tile: 32 x 128 fp32 -> hi/lo bf16 ----
        #pragma unroll
        for (int i = 0; i < 4; i++) {
            int f4  = tid + 256 * i;          // 0..1023
            int row = f4 >> 5;                // 0..31
            int c4  = f4 & 31;                // 0..31
            float4 v = *(const float4*)(Bblk + (size_t)(k0 + row) * N + c4 * 4);
            __nv_bfloat16 h0 = __float2bfloat16(v.x);
            __nv_bfloat16 h1 = __float2bfloat16(v.y);
            __nv_bfloat16 h2 = __float2bfloat16(v.z);
            __nv_bfloat16 h3 = __float2bfloat16(v.w);
            __nv_bfloat16 l0 = __float2bfloat16(v.x - __bfloat162float(h0));
            __nv_bfloat16 l1 = __float2bfloat16(v.y - __bfloat162float(h1));
            __nv_bfloat16 l2 = __float2bfloat16(v.z - __bfloat162float(h2));
            __nv_bfloat16 l3 = __float2bfloat16(v.w - __bfloat162float(h3));
            uint2 ph = make_uint2(pack_bf16x2(h0, h1), pack_bf16x2(h2, h3));
            uint2 pl = make_uint2(pack_bf16x2(l0, l1), pack_bf16x2(l2, l3));
            *(uint2*)&Bs_hi[row * LDB_S + c4 * 4] = ph;
            *(uint2*)&Bs_lo[row * LDB_S + c4 * 4] = pl;
        }
        __syncthreads();

        // ---- 2 k-steps of 16 ----
        #pragma unroll
        for (int ks = 0; ks < 2; ks++) {
            unsigned ah[2][4], al[2][4], bf[16];

            // A hi fragments (2 m-tiles)
            #pragma unroll
            for (int mt = 0; mt < 2; mt++) {
                unsigned addr = smem_addr_u32(&As_hi[(a_row + mt * 16) * LDA_S + ks * 16 + a_col]);
                ldmatrix_x4(ah[mt], addr);
            }
            // B hi fragments (4 pairs = 8 n-tiles)
            #pragma unroll
            for (int ntp = 0; ntp < 4; ntp++) {
                unsigned addr = smem_addr_u32(&Bs_hi[(ks * 16 + b_row) * LDB_S + b_col + ntp * 16]);
                ldmatrix_x4_trans(&bf[ntp * 4], addr);
            }
            // pass 1: Ah * Bh
            #pragma unroll
            for (int mt = 0; mt < 2; mt++)
                #pragma unroll
                for (int nt = 0; nt < 8; nt++)
                    mma_bf16(acc[mt][nt], ah[mt], &bf[nt * 2]);

            // A lo fragments
            #pragma unroll
            for (int mt = 0; mt < 2; mt++) {
                unsigned addr = smem_addr_u32(&As_lo[(a_row + mt * 16) * LDA_S + ks * 16 + a_col]);
                ldmatrix_x4(al[mt], addr);
            }
            // pass 2: Al * Bh
            #pragma unroll
            for (int mt = 0; mt < 2; mt++)
                #pragma unroll
                for (int nt = 0; nt < 8; nt++)
                    mma_bf16(acc[mt][nt], al[mt], &bf[nt * 2]);

            // B lo fragments (overwrite bf)
            #pragma unroll
            for (int ntp = 0; ntp < 4; ntp++) {
                unsigned addr = smem_addr_u32(&Bs_lo[(ks * 16 + b_row) * LDB_S + b_col + ntp * 16]);
                ldmatrix_x4_trans(&bf[ntp * 4], addr);
            }
            // pass 3: Ah * Bl
            #pragma unroll
            for (int mt = 0; mt < 2; mt++)
                #pragma unroll
                for (int nt = 0; nt < 8; nt++)
                    mma_bf16(acc[mt][nt], ah[mt], &bf[nt * 2]);
        }
    }

    // ---- epilogue ----
    const int row_base = by * 128 + wm * 32 + (lane >> 2);
    const int col_base = bx * 128 + wn * 64 + (lane & 3) * 2;
    #pragma unroll
    for (int mt = 0; mt < 2; mt++) {
        #pragma unroll
        for (int nt = 0; nt < 8; nt++) {
            int col = col_base + nt * 8;
            float2 vb;
            if (DO_BIAS) vb = *(const float2*)&bias[col];
            #pragma unroll
            for (int half = 0; half < 2; half++) {
                int row = row_base + mt * 16 + half * 8;
                float v0 = acc[mt][nt][half * 2 + 0];
                float v1 = acc[mt][nt][half * 2 + 1];
                if (DO_BIAS) { v0 += vb.x; v1 += vb.y; }
                if (DO_GELU) { v0 = v0 * normcdff(v0); v1 = v1 * normcdff(v1); }
                size_t off = (size_t)row * N + col;
                if (DO_ADDC) {
                    float2 c = *(const float2*)&Cadd[off];
                    v0 += c.x; v1 += c.y;
                }
                float2 o; o.x = v0; o.y = v1;
                *(float2*)&D[off] = o;
            }
        }
    }
}

// ---------------- flash attention (unchanged) ----------------
__global__ __launch_bounds__(64)
void flash_attn_kernel(const float* __restrict__ qkv, float* __restrict__ out) {
    const int tid = threadIdx.x;
    const int qt = blockIdx.x;
    const int hh = blockIdx.y;
    const int b  = blockIdx.z;

    __shared__ float k_sm[64 * 64];
    __shared__ float v_sm[64 * 64];

    const int q_row = qt * 64 + tid;
    const float* qp = qkv + ((size_t)(b * TT + q_row)) * (3 * INNER) + hh * HDIM;

    float q[64], acc[64];
    #pragma unroll
    for (int d = 0; d < 64; d++) { q[d] = qp[d] * 0.125f; acc[d] = 0.f; }
    float m = -3.0e38f, l = 0.f;

    for (int kt = 0; kt <= qt; kt++) {
        const float* kb = qkv + ((size_t)(b * TT + kt * 64)) * (3 * INNER) + INNER + hh * HDIM;
        const float* vb = kb + INNER;
        __syncthreads();
        for (int r = 0; r < 64; r++) {
            k_sm[r * 64 + tid] = kb[(size_t)r * (3 * INNER) + tid];
            v_sm[r * 64 + tid] = vb[(size_t)r * (3 * INNER) + tid];
        }
        __syncthreads();

        const int valid = q_row - kt * 64;
        #pragma unroll
        for (int c = 0; c < 2; c++) {
            float s[32];
            float mt = -3.0e38f;
            for (int j = 0; j < 32; j++) {
                const int jj = c * 32 + j;
                float sv;
                if (jj <= valid) {
                    sv = 0.f;
                    #pragma unroll
                    for (int d = 0; d < 64; d++) sv += q[d] * k_sm[jj * 64 + d];
                } else {
                    sv = -3.0e38f;
                }
                s[j] = sv;
                mt = fmaxf(mt, sv);
            }
            if (mt > m) {
                float corr = expf(m - mt);
                l *= corr;
                #pragma unroll
                for (int d = 0; d < 64; d++) acc[d] *= corr;
                m = mt;
            }
            for (int j = 0; j < 32; j++) {
                float p = expf(s[j] - m);
                l += p;
                const int jj = c * 32 + j;
                #pragma unroll
                for (int d = 0; d < 64; d++) acc[d] += p * v_sm[jj * 64 + d];
            }
        }
    }

    const float inv = 1.0f / l;
    float* op = out + ((size_t)(b * TT + q_row)) * INNER + hh * HDIM;
    #pragma unroll
    for (int d = 0; d < 64; d++) op[d] = acc[d] * inv;
}

// ---------------- launch ----------------
extern "C" void kernel_launch(void* const* d_in, const int* in_sizes, int n_in,
                              void* d_out, int out_size) {
    const void*      x      = d_in[0];
    const float*     emb    = (const float*)d_in[1];
    const float*     pos    = (const float*)d_in[2];
    const float*     w_qkv  = (const float*)d_in[3];
    const float*     w_out  = (const float*)d_in[4];
    const float*     ln1_g  = (const float*)d_in[5];
    const float*     ln1_b  = (const float*)d_in[6];
    const float*     ln2_g  = (const float*)d_in[7];
    const float*     ln2_b  = (const float*)d_in[8];
    const float*     w_ffn1 = (const float*)d_in[9];
    const float*     b_ffn1 = (const float*)d_in[10];
    const float*     w_ffn2 = (const float*)d_in[11];
    const float*     b_ffn2 = (const float*)d_in[12];
    const float*     w_head = (const float*)d_in[13];
    const float*     b_head = (const float*)d_in[14];
    float* out = (float*)d_out;

    float *h, *h1, *qkv, *att, *ff1;
    cudaGetSymbolAddress((void**)&h,   g_h);
    cudaGetSymbolAddress((void**)&h1,  g_h1);
    cudaGetSymbolAddress((void**)&qkv, g_qkv);
    cudaGetSymbolAddress((void**)&att, g_att);
    cudaGetSymbolAddress((void**)&ff1, g_ff1);

    // 1. embed + pos + ln1
    embed_ln_kernel<<<TOK, 256>>>(x, emb, pos, ln1_g, ln1_b, h, h1);

    // 2. qkv = h1 @ w_qkv   (4096 x 3072 x 1024)
    gemm_tc_kernel<0,0,0><<<dim3(3 * INNER / 128, TOK / 128), 256>>>(
        TOK, 3 * INNER, DD, h1, w_qkv, nullptr, nullptr, qkv);

    // 3. flash attention -> att
    flash_attn_kernel<<<dim3(TT / 64, HH, BATCH), 64>>>(qkv, att);

    // 4. h = h + att @ w_out  (4096 x 1024 x 1024)
    gemm_tc_kernel<0,1,0><<<dim3(DD / 128, TOK / 128), 256>>>(
        TOK, DD, INNER, att, w_out, h, nullptr, h);

    // 5. h2 = ln2(h)
    ln_kernel<<<TOK, 256>>>(h, ln2_g, ln2_b, h1);

    // 6. ff1 = gelu(h2 @ w_ffn1 + b_ffn1)  (4096 x 4096 x 1024)
    gemm_tc_kernel<1,0,1><<<dim3(FFN / 128, TOK / 128), 256>>>(
        TOK, FFN, DD, h1, w_ffn1, nullptr, b_ffn1, ff1);

    // 7. h = h + ff1 @ w_ffn2 + b_ffn2  (4096 x 1024 x 4096)
    gemm_tc_kernel<1,1,0><<<dim3(DD / 128, TOK / 128), 256>>>(
        TOK, DD, FFN, ff1, w_ffn2, h, b_ffn2, h);

    // 8. logits = h @ w_head + b_head  (4096 x 32000 x 1024)
    gemm_tc_kernel<1,0,0><<<dim3(VOCAB / 128, TOK / 128), 256>>>(
        TOK, VOCAB, DD, h, w_head, nullptr, b_head, out);
}

// round 4
// speedup vs baseline: 2.3948x; 1.0032x over previous
#include <cuda_runtime.h>
#include <cuda_bf16.h>
#include <math.h>

// Problem constants
#define BATCH 2
#define TT    2048
#define TOK   (BATCH * TT)      // 4096 tokens
#define DD    1024
#define HH    16
#define HDIM  64
#define INNER (HH * HDIM)       // 1024
#define VOCAB 32000
#define FFN   (4 * DD)          // 4096

// ---------------- scratch (static device globals; no allocation) ----------------
__device__ float g_h  [TOK * DD];
__device__ float g_h1 [TOK * DD];
__device__ float g_qkv[TOK * 3 * INNER];
__device__ float g_att[TOK * INNER];
__device__ float g_ff1[TOK * FFN];

// ---------------- block reduction (256 threads) ----------------
__device__ __forceinline__ float block_sum256(float v) {
    __shared__ float red[8];
    const unsigned FULL = 0xffffffffu;
    #pragma unroll
    for (int o = 16; o > 0; o >>= 1) v += __shfl_down_sync(FULL, v, o);
    __syncthreads();
    if ((threadIdx.x & 31) == 0) red[threadIdx.x >> 5] = v;
    __syncthreads();
    float s = 0.f;
    #pragma unroll
    for (int i = 0; i < 8; i++) s += red[i];
    return s;
}

// ---------------- token fetch: robust to int32 vs int64 layout ----------------
__device__ __forceinline__ int fetch_token(const void* xraw, int t) {
    const int* x32 = (const int*)xraw;
    bool is64 = true;
    #pragma unroll
    for (int i = 0; i < 8; i++) {
        if (x32[2 * i + 1] != 0) is64 = false;
    }
    return is64 ? (int)(((const long long*)xraw)[t]) : x32[t];
}

// ---------------- embed + pos + LN1 ----------------
__global__ void embed_ln_kernel(const void* __restrict__ x,
                                const float* __restrict__ emb,
                                const float* __restrict__ pos,
                                const float* __restrict__ g,
                                const float* __restrict__ b,
                                float* __restrict__ h,
                                float* __restrict__ h1) {
    const int t    = blockIdx.x;
    const int tpos = t & (TT - 1);
    const int tok = fetch_token(x, t);
    const float* e = emb + (size_t)tok * DD;
    const float* p = pos + (size_t)tpos * DD;

    float local[4];
    float s = 0.f;
    #pragma unroll
    for (int i = 0; i < 4; i++) {
        int idx = threadIdx.x + i * 256;
        float v = e[idx] + p[idx];
        local[i] = v;
        h[(size_t)t * DD + idx] = v;
        s += v;
    }
    float S = block_sum256(s);
    float mu = S * (1.0f / DD);
    float s2 = 0.f;
    #pragma unroll
    for (int i = 0; i < 4; i++) { float d = local[i] - mu; s2 += d * d; }
    float V = block_sum256(s2);
    float rstd = rsqrtf(V * (1.0f / DD) + 1e-5f);
    #pragma unroll
    for (int i = 0; i < 4; i++) {
        int idx = threadIdx.x + i * 256;
        h1[(size_t)t * DD + idx] = (local[i] - mu) * rstd * g[idx] + b[idx];
    }
}

// ---------------- LN only ----------------
__global__ void ln_kernel(const float* __restrict__ h,
                          const float* __restrict__ g,
                          const float* __restrict__ b,
                          float* __restrict__ out) {
    const int t = blockIdx.x;
    float local[4];
    float s = 0.f;
    #pragma unroll
    for (int i = 0; i < 4; i++) {
        int idx = threadIdx.x + i * 256;
        float v = h[(size_t)t * DD + idx];
        local[i] = v;
        s += v;
    }
    float S = block_sum256(s);
    float mu = S * (1.0f / DD);
    float s2 = 0.f;
    #pragma unroll
    for (int i = 0; i < 4; i++) { float d = local[i] - mu; s2 += d * d; }
    float V = block_sum256(s2);
    float rstd = rsqrtf(V * (1.0f / DD) + 1e-5f);
    #pragma unroll
    for (int i = 0; i < 4; i++) {
        int idx = threadIdx.x + i * 256;
        out[(size_t)t * DD + idx] = (local[i] - mu) * rstd * g[idx] + b[idx];
    }
}

// ================= tensor-core GEMM (bf16x3 split emulating fp32) =================
// D(MxN) = A(MxK) @ B(KxN) [+bias] [gelu] [+C]
// A,B,C,D fp32 row-major. A/B split on the fly into bf16 hi+lo.
// CTA tile 128x128, BK=32, 256 threads = 8 warps in 4(M) x 2(N); warp tile 32x64.

#define LDA_S 40    // A smem row stride (elems): 128 rows x 40
#define LDB_S 136   // B smem row stride (elems): 32 rows x 136

__device__ __forceinline__ unsigned smem_addr_u32(const void* p) {
    return (unsigned)__cvta_generic_to_shared(p);
}

__device__ __forceinline__ void ldmatrix_x4(unsigned* r, unsigned addr) {
    asm volatile("ldmatrix.sync.aligned.m8n8.x4.shared.b16 {%0,%1,%2,%3}, [%4];"
                 : "=r"(r[0]), "=r"(r[1]), "=r"(r[2]), "=r"(r[3]) : "r"(addr));
}
__device__ __forceinline__ void ldmatrix_x4_trans(unsigned* r, unsigned addr) {
    asm volatile("ldmatrix.sync.aligned.m8n8.x4.trans.shared.b16 {%0,%1,%2,%3}, [%4];"
                 : "=r"(r[0]), "=r"(r[1]), "=r"(r[2]), "=r"(r[3]) : "r"(addr));
}
__device__ __forceinline__ void mma_bf16(float* c, const unsigned* a, const unsigned* b) {
    asm volatile("mma.sync.aligned.m16n8k16.row.col.f32.bf16.bf16.f32 "
                 "{%0,%1,%2,%3}, {%4,%5,%6,%7}, {%8,%9}, {%0,%1,%2,%3};"
                 : "+f"(c[0]), "+f"(c[1]), "+f"(c[2]), "+f"(c[3])
                 : "r"(a[0]), "r"(a[1]), "r"(a[2]), "r"(a[3]), "r"(b[0]), "r"(b[1]));
}

__device__ __forceinline__ unsigned pack_bf16x2(__nv_bfloat16 a, __nv_bfloat16 b) {
    __nv_bfloat162 p = __halves2bfloat162(a, b);   // (lo=a, hi=b) -> bits [a | b<<16]
    return *(unsigned*)&p;
}

template<int DO_BIAS, int DO_ADDC, int DO_GELU>
__global__ __launch_bounds__(256)
void gemm_tc_kernel(int M, int N, int K,
                    const float* __restrict__ A,
                    const float* __restrict__ B,
                    const float* __restrict__ Cadd,
                    const float* __restrict__ bias,
                    float* __restrict__ D) {
    __shared__ __align__(16) __nv_bfloat16 As_hi[128 * LDA_S];
    __shared__ __align__(16) __nv_bfloat16 As_lo[128 * LDA_S];
    __shared__ __align__(16) __nv_bfloat16 Bs_hi[32 * LDB_S];
    __shared__ __align__(16) __nv_bfloat16 Bs_lo[32 * LDB_S];

    const int tid   = threadIdx.x;
    const int lane  = tid & 31;
    const int warp  = tid >> 5;        // 0..7
    const int wm    = warp & 3;        // M group (0..3) -> rows wm*32
    const int wn    = warp >> 2;       // N group (0..1) -> cols wn*64

    const int bx = blockIdx.x;         // N tile
    const int by = blockIdx.y;         // M tile

    const float* Ablk = A + (size_t)by * 128 * K;
    const float* Bblk = B + (size_t)bx * 128;

    float acc[2][8][4];
    #pragma unroll
    for (int i = 0; i < 2; i++)
        #pragma unroll
        for (int j = 0; j < 8; j++)
            #pragma unroll
            for (int q = 0; q < 4; q++) acc[i][j][q] = 0.f;

    // ldmatrix source addresses (per-lane), as element offsets
    // A: row = wm*32 + mt*16 + (lane&15), col = ks*16 + (lane>>4)*8
    const int a_row = wm * 32 + (lane & 15);
    const int a_col = (lane >> 4) * 8;
    // B: row = ks*16 + (lane&15), col = wn*64 + ntp*16 + (lane>>4)*8
    const int b_row = (lane & 15);
    const int b_col = wn * 64 + (lane >> 4) * 8;

    for (int k0 = 0; k0 < K; k0 += 32) {
        __syncthreads();   // protect smem from previous iteration's reads

        // ---- load + split A tile: 128 x 32 fp32 -> hi/lo bf16 ----
        #pragma unroll
        for (int i = 0; i < 4; i++) {
            int f4  = tid + 256 * i;          // 0..1023
            int row = f4 >> 3;                // 0..127
            int c4  = f4 & 7;                 // 0..7
            float4 v = *(const float4*)(Ablk + (size_t)row * K + k0 + c4 * 4);
            __nv_bfloat16 h0 = __float2bfloat16(v.x);
            __nv_bfloat16 h1 = __float2bfloat16(v.y);
            __nv_bfloat16 h2 = __float2bfloat16(v.z);
            __nv_bfloat16 h3 = __float2bfloat16(v.w);
            __nv_bfloat16 l0 = __float2bfloat16(v.x - __bfloat162float(h0));
            __nv_bfloat16 l1 = __float2bfloat16(v.y - __bfloat162float(h1));
            __nv_bfloat16 l2 = __float2bfloat16(v.z - __bfloat162float(h2));
            __nv_bfloat16 l3 = __float2bfloat16(v.w - __bfloat162float(h3));
            uint2 ph = make_uint2(pack_bf16x2(h0, h1), pack_bf16x2(h2, h3));
            uint2 pl = make_uint2(pack_bf16x2(l0, l1), pack_bf16x2(l2, l3));
            *(uint2*)&As_hi[row * LDA_S + c4 * 4] = ph;
            *(uint2*)&As_lo[row * LDA_S + c4 * 4] = pl;
        }
        // ---- load + split B tile: 32 x 128 fp32 -> hi/lo bf16 ----
        #pragma unroll
        for (int i = 0; i < 4; i++) {
            int f4  = tid + 256 * i;          // 0..1023
            int row = f4 >> 5;                // 0..31
            int c4  = f4 & 31;                // 0..31
            float4 v = *(const float4*)(Bblk + (size_t)(k0 + row) * N + c4 * 4);
            __nv_bfloat16 h0 = __float2bfloat16(v.x);
            __nv_bfloat16 h1 = __float2bfloat16(v.y);
            __nv_bfloat16 h2 = __float2bfloat16(v.z);
            __nv_bfloat16 h3 = __float2bfloat16(v.w);
            __nv_bfloat16 l0 = __float2bfloat16(v.x - __bfloat162float(h0));
            __nv_bfloat16 l1 = __float2bfloat16(v.y - __bfloat162float(h1));
            __nv_bfloat16 l2 = __float2bfloat16(v.z - __bfloat162float(h2));
            __nv_bfloat16 l3 = __float2bfloat16(v.w - __bfloat162float(h3));
            uint2 ph = make_uint2(pack_bf16x2(h0, h1), pack_bf16x2(h2, h3));
            uint2 pl = make_uint2(pack_bf16x2(l0, l1), pack_bf16x2(l2, l3));
            *(uint2*)&Bs_hi[row * LDB_S + c4 * 4] = ph;
            *(uint2*)&Bs_lo[row * LDB_S + c4 * 4] = pl;
        }
        __syncthreads();

        // ---- 2 k-steps of 16 ----
        #pragma unroll
        for (int ks = 0; ks < 2; ks++) {
            unsigned ah[2][4], al[2][4], bf[16];

            // A hi fragments (2 m-tiles)
            #pragma unroll
            for (int mt = 0; mt < 2; mt++) {
                unsigned addr = smem_addr_u32(&As_hi[(a_row + mt * 16) * LDA_S + ks * 16 + a_col]);
                ldmatrix_x4(ah[mt], addr);
            }
            // B hi fragments (4 pairs = 8 n-tiles)
            #pragma unroll
            for (int ntp = 0; ntp < 4; ntp++) {
                unsigned addr = smem_addr_u32(&Bs_hi[(ks * 16 + b_row) * LDB_S + b_col + ntp * 16]);
                ldmatrix_x4_trans(&bf[ntp * 4], addr);
            }
            // pass 1: Ah * Bh
            #pragma unroll
            for (int mt = 0; mt < 2; mt++)
                #pragma unroll
                for (int nt = 0; nt < 8; nt++)
                    mma_bf16(acc[mt][nt], ah[mt], &bf[nt * 2]);

            // A lo fragments
            #pragma unroll
            for (int mt = 0; mt < 2; mt++) {
                unsigned addr = smem_addr_u32(&As_lo[(a_row + mt * 16) * LDA_S + ks * 16 + a_col]);
                ldmatrix_x4(al[mt], addr);
            }
            // pass 2: Al * Bh
            #pragma unroll
            for (int mt = 0; mt < 2; mt++)
                #pragma unroll
                for (int nt = 0; nt < 8; nt++)
                    mma_bf16(acc[mt][nt], al[mt], &bf[nt * 2]);

            // B lo fragments (overwrite bf)
            #pragma unroll
            for (int ntp = 0; ntp < 4; ntp++) {
                unsigned addr = smem_addr_u32(&Bs_lo[(ks * 16 + b_row) * LDB_S + b_col + ntp * 16]);
                ldmatrix_x4_trans(&bf[ntp * 4], addr);
            }
            // pass 3: Ah * Bl
            #pragma unroll
            for (int mt = 0; mt < 2; mt++)
                #pragma unroll
                for (int nt = 0; nt < 8; nt++)
                    mma_bf16(acc[mt][nt], ah[mt], &bf[nt * 2]);
        }
    }

    // ---- epilogue ----
    const int row_base = by * 128 + wm * 32 + (lane >> 2);
    const int col_base = bx * 128 + wn * 64 + (lane & 3) * 2;
    #pragma unroll
    for (int mt = 0; mt < 2; mt++) {
        #pragma unroll
        for (int nt = 0; nt < 8; nt++) {
            int col = col_base + nt * 8;
            float2 vb;
            if (DO_BIAS) vb = *(const float2*)&bias[col];
            #pragma unroll
            for (int half = 0; half < 2; half++) {
                int row = row_base + mt * 16 + half * 8;
                float v0 = acc[mt][nt][half * 2 + 0];
                float v1 = acc[mt][nt][half * 2 + 1];
                if (DO_BIAS) { v0 += vb.x; v1 += vb.y; }
                if (DO_GELU) { v0 = v0 * normcdff(v0); v1 = v1 * normcdff(v1); }
                size_t off = (size_t)row * N + col;
                if (DO_ADDC) {
                    float2 c = *(const float2*)&Cadd[off];
                    v0 += c.x; v1 += c.y;
                }
                float2 o; o.x = v0; o.y = v1;
                *(float2*)&D[off] = o;
            }
        }
    }
}

// ---------------- flash attention (unchanged) ----------------
__global__ __launch_bounds__(64)
void flash_attn_kernel(const float* __restrict__ qkv, float* __restrict__ out) {
    const int tid = threadIdx.x;
    const int qt = blockIdx.x;
    const int hh = blockIdx.y;
    const int b  = blockIdx.z;

    __shared__ float k_sm[64 * 64];
    __shared__ float v_sm[64 * 64];

    const int q_row = qt * 64 + tid;
    const float* qp = qkv + ((size_t)(b * TT + q_row)) * (3 * INNER) + hh * HDIM;

    float q[64], acc[64];
    #pragma unroll
    for (int d = 0; d < 64; d++) { q[d] = qp[d] * 0.125f; acc[d] = 0.f; }
    float m = -3.0e38f, l = 0.f;

    for (int kt = 0; kt <= qt; kt++) {
        const float* kb = qkv + ((size_t)(b * TT + kt * 64)) * (3 * INNER) + INNER + hh * HDIM;
        const float* vb = kb + INNER;
        __syncthreads();
        for (int r = 0; r < 64; r++) {
            k_sm[r * 64 + tid] = kb[(size_t)r * (3 * INNER) + tid];
            v_sm[r * 64 + tid] = vb[(size_t)r * (3 * INNER) + tid];
        }
        __syncthreads();

        const int valid = q_row - kt * 64;
        #pragma unroll
        for (int c = 0; c < 2; c++) {
            float s[32];
            float mt = -3.0e38f;
            for (int j = 0; j < 32; j++) {
                const int jj = c * 32 + j;
                float sv;
                if (jj <= valid) {
                    sv = 0.f;
                    #pragma unroll
                    for (int d = 0; d < 64; d++) sv += q[d] * k_sm[jj * 64 + d];
                } else {
                    sv = -3.0e38f;
                }
                s[j] = sv;
                mt = fmaxf(mt, sv);
            }
            if (mt > m) {
                float corr = expf(m - mt);
                l *= corr;
                #pragma unroll
                for (int d = 0; d < 64; d++) acc[d] *= corr;
                m = mt;
            }
            for (int j = 0; j < 32; j++) {
                float p = expf(s[j] - m);
                l += p;
                const int jj = c * 32 + j;
                #pragma unroll
                for (int d = 0; d < 64; d++) acc[d] += p * v_sm[jj * 64 + d];
            }
        }
    }

    const float inv = 1.0f / l;
    float* op = out + ((size_t)(b * TT + q_row)) * INNER + hh * HDIM;
    #pragma unroll
    for (int d = 0; d < 64; d++) op[d] = acc[d] * inv;
}

// ---------------- launch ----------------
extern "C" void kernel_launch(void* const* d_in, const int* in_sizes, int n_in,
                              void* d_out, int out_size) {
    const void*      x      = d_in[0];
    const float*     emb    = (const float*)d_in[1];
    const float*     pos    = (const float*)d_in[2];
    const float*     w_qkv  = (const float*)d_in[3];
    const float*     w_out  = (const float*)d_in[4];
    const float*     ln1_g  = (const float*)d_in[5];
    const float*     ln1_b  = (const float*)d_in[6];
    const float*     ln2_g  = (const float*)d_in[7];
    const float*     ln2_b  = (const float*)d_in[8];
    const float*     w_ffn1 = (const float*)d_in[9];
    const float*     b_ffn1 = (const float*)d_in[10];
    const float*     w_ffn2 = (const float*)d_in[11];
    const float*     b_ffn2 = (const float*)d_in[12];
    const float*     w_head = (const float*)d_in[13];
    const float*     b_head = (const float*)d_in[14];
    float* out = (float*)d_out;

    float *h, *h1, *qkv, *att, *ff1;
    cudaGetSymbolAddress((void**)&h,   g_h);
    cudaGetSymbolAddress((void**)&h1,  g_h1);
    cudaGetSymbolAddress((void**)&qkv, g_qkv);
    cudaGetSymbolAddress((void**)&att, g_att);
    cudaGetSymbolAddress((void**)&ff1, g_ff1);

    // 1. embed + pos + ln1
    embed_ln_kernel<<<TOK, 256>>>(x, emb, pos, ln1_g, ln1_b, h, h1);

    // 2. qkv = h1 @ w_qkv   (4096 x 3072 x 1024)
    gemm_tc_kernel<0,0,0><<<dim3(3 * INNER / 128, TOK / 128), 256>>>(
        TOK, 3 * INNER, DD, h1, w_qkv, nullptr, nullptr, qkv);

    // 3. flash attention -> att
    flash_attn_kernel<<<dim3(TT / 64, HH, BATCH), 64>>>(qkv, att);

    // 4. h = h + att @ w_out  (4096 x 1024 x 1024)
    gemm_tc_kernel<0,1,0><<<dim3(DD / 128, TOK / 128), 256>>>(
        TOK, DD, INNER, att, w_out, h, nullptr, h);

    // 5. h2 = ln2(h)
    ln_kernel<<<TOK, 256>>>(h, ln2_g, ln2_b, h1);

    // 6. ff1 = gelu(h2 @ w_ffn1 + b_ffn1)  (4096 x 4096 x 1024)
    gemm_tc_kernel<1,0,1><<<dim3(FFN / 128, TOK / 128), 256>>>(
        TOK, FFN, DD, h1, w_ffn1, nullptr, b_ffn1, ff1);

    // 7. h = h + ff1 @ w_ffn2 + b_ffn2  (4096 x 1024 x 4096)
    gemm_tc_kernel<1,1,0><<<dim3(DD / 128, TOK / 128), 256>>>(
        TOK, DD, FFN, ff1, w_ffn2, h, b_ffn2, h);

    // 8. logits = h @ w_head + b_head  (4096 x 32000 x 1024)
    gemm_tc_kernel<1,0,0><<<dim3(VOCAB / 128, TOK / 128), 256>>>(
        TOK, VOCAB, DD, h, w_head, nullptr, b_head, out);
}